// round 2
// baseline (speedup 1.0000x reference)
#include <cuda_runtime.h>
#include <math.h>

#define Npts   16384
#define PER    2048
#define Mc     4096
#define Kn     64
#define R2v    0.0625f
#define CIN    128
#define FD     259
#define FSTRIDE 260
#define HID    256
#define COUT   256
#define CSTRIDE 4

__device__ int g_nbr[Mc * Kn];
__device__ int g_cnt[Mc];

// ---------------------------------------------------------------------------
// Kernel 1: ball query. One block per center. Collect in-radius candidates
// (same batch block), bitonic-sort by packed (d2|idx) key, keep 64 nearest.
// ---------------------------------------------------------------------------
__global__ void __launch_bounds__(256) ball_query_kernel(const float* __restrict__ pos)
{
    __shared__ unsigned long long s[PER];
    __shared__ int cnt;
    int m = blockIdx.x;
    int c = m * CSTRIDE;
    int base = (c / PER) * PER;

    if (threadIdx.x == 0) cnt = 0;
    __syncthreads();

    float px = pos[c * 3 + 0], py = pos[c * 3 + 1], pz = pos[c * 3 + 2];
    for (int t = threadIdx.x; t < PER; t += blockDim.x) {
        int n = base + t;
        float dx = pos[n * 3 + 0] - px;
        float dy = pos[n * 3 + 1] - py;
        float dz = pos[n * 3 + 2] - pz;
        float d2 = dx * dx + dy * dy + dz * dz;
        if (d2 <= R2v) {
            int p = atomicAdd(&cnt, 1);
            s[p] = (((unsigned long long)__float_as_uint(d2)) << 32) | (unsigned)n;
        }
    }
    __syncthreads();
    int count = cnt;

    if (count > Kn) {
        int P = Kn;
        while (P < count) P <<= 1;
        for (int t = count + threadIdx.x; t < P; t += blockDim.x) s[t] = ~0ull;
        __syncthreads();
        for (int k2 = 2; k2 <= P; k2 <<= 1) {
            for (int j = k2 >> 1; j > 0; j >>= 1) {
                for (int i = threadIdx.x; i < P; i += blockDim.x) {
                    int ix = i ^ j;
                    if (ix > i) {
                        unsigned long long a = s[i], b = s[ix];
                        bool up = ((i & k2) == 0);
                        if ((a > b) == up) { s[i] = b; s[ix] = a; }
                    }
                }
                __syncthreads();
            }
        }
    }
    int nv = count < Kn ? count : Kn;
    for (int k = threadIdx.x; k < Kn; k += blockDim.x)
        g_nbr[m * Kn + k] = (k < nv) ? (int)(unsigned)(s[k] & 0xffffffffu) : c;
    if (threadIdx.x == 0) g_cnt[m] = nv;
}

// ---------------------------------------------------------------------------
// Kernel 2: EdgeConv MLP + masked max. One block (256 thr) per center.
// SMEM: F[64][260] feats, H[64][256] hidden. 8x8 register tile per thread,
// f32x2 packed FMAs. Warp == fixed row-group -> SMEM A-reads are broadcasts.
// ---------------------------------------------------------------------------
__global__ void __launch_bounds__(256, 1) edge_mlp_kernel(
    const float* __restrict__ x,  const float* __restrict__ pos,
    const float* __restrict__ lframes,
    const float* __restrict__ W1, const float* __restrict__ b1,
    const float* __restrict__ W2, const float* __restrict__ b2,
    float* __restrict__ out)
{
    extern __shared__ float smem[];
    float* F   = smem;                       // [64][260]
    float* H   = smem + Kn * FSTRIDE;        // [64][256]
    float* XD  = H + Kn * HID;               // [128]
    float* AUX = XD + 128;                   // [12] pos_dst(3), lframe(9)
    float* RED = F;                          // overlay after GEMM1 reads done

    int m = blockIdx.x;
    int c = m * CSTRIDE;
    int tid = threadIdx.x;
    int ty = tid >> 5;                       // warp id 0..7 (row group)
    int tx = tid & 31;                       // lane   0..31 (col group)

    if (tid < 128)                XD[tid] = x[(long long)c * CIN + tid];
    if (tid >= 128 && tid < 131)  AUX[tid - 128] = pos[c * 3 + (tid - 128)];
    if (tid >= 131 && tid < 140)  AUX[3 + tid - 131] = lframes[c * 9 + (tid - 131)];
    __syncthreads();

    int nv = g_cnt[m];

    // Gather feature rows: [x_nbr(128) | x_dst(128) | rel_loc(3)]
    for (int k = ty; k < Kn; k += 8) {
        int n = g_nbr[m * Kn + k];
        float4 v = __ldg((const float4*)(x + (long long)n * CIN) + tx);
        ((float4*)(F + k * FSTRIDE))[tx] = v;
        ((float4*)(F + k * FSTRIDE + CIN))[tx] = ((const float4*)XD)[tx];
        if (tx < 3) {
            float rx = pos[n * 3 + 0] - AUX[0];
            float ry = pos[n * 3 + 1] - AUX[1];
            float rz = pos[n * 3 + 2] - AUX[2];
            F[k * FSTRIDE + 256 + tx] =
                AUX[3 + tx * 3 + 0] * rx + AUX[3 + tx * 3 + 1] * ry + AUX[3 + tx * 3 + 2] * rz;
        }
    }
    __syncthreads();

    unsigned long long acc[32];

    // ---------------- GEMM1: H = relu(F @ W1 + b1) ----------------
    #pragma unroll
    for (int i = 0; i < 32; i++) acc[i] = 0ull;
    {
        const float* frow = F + (ty * 8) * FSTRIDE;
        #pragma unroll 2
        for (int kk = 0; kk < FD; kk++) {
            const float4* wp = (const float4*)(W1 + (long long)kk * HID + tx * 8);
            float4 w0 = __ldg(wp);
            float4 w1v = __ldg(wp + 1);
            unsigned long long bb0, bb1, bb2, bb3;
            asm("mov.b64 %0,{%1,%2};" : "=l"(bb0) : "f"(w0.x), "f"(w0.y));
            asm("mov.b64 %0,{%1,%2};" : "=l"(bb1) : "f"(w0.z), "f"(w0.w));
            asm("mov.b64 %0,{%1,%2};" : "=l"(bb2) : "f"(w1v.x), "f"(w1v.y));
            asm("mov.b64 %0,{%1,%2};" : "=l"(bb3) : "f"(w1v.z), "f"(w1v.w));
            #pragma unroll
            for (int r = 0; r < 8; r++) {
                float a = frow[r * FSTRIDE + kk];
                unsigned long long aa;
                asm("mov.b64 %0,{%1,%1};" : "=l"(aa) : "f"(a));
                asm("fma.rn.f32x2 %0,%1,%2,%0;" : "+l"(acc[r * 4 + 0]) : "l"(aa), "l"(bb0));
                asm("fma.rn.f32x2 %0,%1,%2,%0;" : "+l"(acc[r * 4 + 1]) : "l"(aa), "l"(bb1));
                asm("fma.rn.f32x2 %0,%1,%2,%0;" : "+l"(acc[r * 4 + 2]) : "l"(aa), "l"(bb2));
                asm("fma.rn.f32x2 %0,%1,%2,%0;" : "+l"(acc[r * 4 + 3]) : "l"(aa), "l"(bb3));
            }
        }
    }
    {
        float bv[8];
        #pragma unroll
        for (int q = 0; q < 8; q++) bv[q] = b1[tx * 8 + q];
        #pragma unroll
        for (int r = 0; r < 8; r++) {
            int row = ty * 8 + r;
            #pragma unroll
            for (int q = 0; q < 4; q++) {
                float lo, hi;
                asm("mov.b64 {%0,%1},%2;" : "=f"(lo), "=f"(hi) : "l"(acc[r * 4 + q]));
                lo = fmaxf(lo + bv[q * 2 + 0], 0.f);
                hi = fmaxf(hi + bv[q * 2 + 1], 0.f);
                H[row * HID + tx * 8 + q * 2 + 0] = lo;
                H[row * HID + tx * 8 + q * 2 + 1] = hi;
            }
        }
    }
    __syncthreads();

    // ---------------- GEMM2: msg = H @ W2 (+b2 folded post-max) ----------------
    #pragma unroll
    for (int i = 0; i < 32; i++) acc[i] = 0ull;
    {
        const float* hrow = H + (ty * 8) * HID;
        #pragma unroll 2
        for (int kk = 0; kk < HID; kk++) {
            const float4* wp = (const float4*)(W2 + (long long)kk * COUT + tx * 8);
            float4 w0 = __ldg(wp);
            float4 w1v = __ldg(wp + 1);
            unsigned long long bb0, bb1, bb2, bb3;
            asm("mov.b64 %0,{%1,%2};" : "=l"(bb0) : "f"(w0.x), "f"(w0.y));
            asm("mov.b64 %0,{%1,%2};" : "=l"(bb1) : "f"(w0.z), "f"(w0.w));
            asm("mov.b64 %0,{%1,%2};" : "=l"(bb2) : "f"(w1v.x), "f"(w1v.y));
            asm("mov.b64 %0,{%1,%2};" : "=l"(bb3) : "f"(w1v.z), "f"(w1v.w));
            #pragma unroll
            for (int r = 0; r < 8; r++) {
                float a = hrow[r * HID + kk];
                unsigned long long aa;
                asm("mov.b64 %0,{%1,%1};" : "=l"(aa) : "f"(a));
                asm("fma.rn.f32x2 %0,%1,%2,%0;" : "+l"(acc[r * 4 + 0]) : "l"(aa), "l"(bb0));
                asm("fma.rn.f32x2 %0,%1,%2,%0;" : "+l"(acc[r * 4 + 1]) : "l"(aa), "l"(bb1));
                asm("fma.rn.f32x2 %0,%1,%2,%0;" : "+l"(acc[r * 4 + 2]) : "l"(aa), "l"(bb2));
                asm("fma.rn.f32x2 %0,%1,%2,%0;" : "+l"(acc[r * 4 + 3]) : "l"(aa), "l"(bb3));
            }
        }
    }

    // masked max over this thread's 8 rows (edge k = ty*8+r valid iff k < nv)
    float cmax[8];
    #pragma unroll
    for (int q = 0; q < 8; q++) cmax[q] = -3.402823466e38f;
    #pragma unroll
    for (int r = 0; r < 8; r++) {
        if (ty * 8 + r < nv) {
            #pragma unroll
            for (int q = 0; q < 4; q++) {
                float lo, hi;
                asm("mov.b64 {%0,%1},%2;" : "=f"(lo), "=f"(hi) : "l"(acc[r * 4 + q]));
                cmax[q * 2 + 0] = fmaxf(cmax[q * 2 + 0], lo);
                cmax[q * 2 + 1] = fmaxf(cmax[q * 2 + 1], hi);
            }
        }
    }
    __syncthreads();   // all GEMM reads done before overlaying RED on F
    #pragma unroll
    for (int q = 0; q < 8; q++) RED[ty * 256 + tx * 8 + q] = cmax[q];
    __syncthreads();
    {
        int col = tid;
        float v = RED[col];
        #pragma unroll
        for (int t = 1; t < 8; t++) v = fmaxf(v, RED[t * 256 + col]);
        out[(long long)m * COUT + col] = v + b2[col];   // nv >= 1 always (center itself)
    }
}

// ---------------------------------------------------------------------------
// Kernel 3: auxiliary tuple outputs (pos_dst, batch_dst, lframes_dst)
// ---------------------------------------------------------------------------
__global__ void extras_kernel(const float* __restrict__ pos, const int* __restrict__ batch,
                              const float* __restrict__ lframes, float* __restrict__ out)
{
    int m = blockIdx.x * blockDim.x + threadIdx.x;
    if (m >= Mc) return;
    int c = m * CSTRIDE;
    long long o = (long long)Mc * COUT;
    out[o + m * 3 + 0] = pos[c * 3 + 0];
    out[o + m * 3 + 1] = pos[c * 3 + 1];
    out[o + m * 3 + 2] = pos[c * 3 + 2];
    o += (long long)Mc * 3;
    out[o + m] = (float)batch[c];
    o += Mc;
    #pragma unroll
    for (int j = 0; j < 9; j++) out[o + m * 9 + j] = lframes[c * 9 + j];
}

// ---------------------------------------------------------------------------
extern "C" void kernel_launch(void* const* d_in, const int* in_sizes, int n_in,
                              void* d_out, int out_size)
{
    const float* x       = (const float*)d_in[0];
    const float* pos     = (const float*)d_in[1];
    const int*   batch   = (const int*)  d_in[2];
    const float* lframes = (const float*)d_in[3];
    const float* W1      = (const float*)d_in[4];
    const float* b1      = (const float*)d_in[5];
    const float* W2      = (const float*)d_in[6];
    const float* b2      = (const float*)d_in[7];
    float* out = (float*)d_out;

    int smem_bytes = (Kn * FSTRIDE + Kn * HID + 128 + 16) * (int)sizeof(float);
    cudaFuncSetAttribute(edge_mlp_kernel,
                         cudaFuncAttributeMaxDynamicSharedMemorySize, smem_bytes);

    ball_query_kernel<<<Mc, 256>>>(pos);
    edge_mlp_kernel<<<Mc, 256, smem_bytes>>>(x, pos, lframes, W1, b1, W2, b2, out);

    long long full = (long long)Mc * COUT + (long long)Mc * 13;
    if ((long long)out_size >= full)
        extras_kernel<<<(Mc + 255) / 256, 256>>>(pos, batch, lframes, out);
}